// round 2
// baseline (speedup 1.0000x reference)
#include <cuda_runtime.h>

#define BATCH   262144
#define T_STEPS 20
#define BETAF   0.9f
#define THRESHF 1.0f

using u64 = unsigned long long;

// ---- dynamic smem layout (u64 units) ----
// Weights pair-packed over outputs: w[i][q][p] = (W[2*(q*PAIRQ+p)][i], W[2*(q*PAIRQ+p)+1][i])
// QS = per-quarter stride (pairQ + pad, kept even for LDS.128 and bank spread)
#define QS1 10
#define QS2 6
#define QS3 6
#define QS4 4
#define QS5 2
#define W1_OFF 0
#define W2_OFF (W1_OFF + 10 * 4 * QS1)   // 400
#define W3_OFF (W2_OFF + 64 * 4 * QS2)   // 1936
#define W4_OFF (W3_OFF + 32 * 4 * QS3)   // 2704
#define W5_OFF (W4_OFF + 32 * 4 * QS4)   // 3216
#define SPK_OFF (W5_OFF + 16 * 4 * QS5)  // 3344
#define ESTRIDE 146                       // per-element spike slots: L1@0(64) L2@64(32) L3@96(32) L4@128(16) +2 pad
#define SMEM_U64 (SPK_OFF + 64 * ESTRIDE) // 12688 u64 = 101504 B

__device__ __forceinline__ u64 pack2(float lo, float hi) {
    u64 r; asm("mov.b64 %0, {%1, %2};" : "=l"(r) : "f"(lo), "f"(hi)); return r;
}
__device__ __forceinline__ void unpack2(u64 v, float &lo, float &hi) {
    asm("mov.b64 {%0, %1}, %2;" : "=f"(lo), "=f"(hi) : "l"(v));
}
// Packed dual fp32 FMA on the fma pipe (2 MACs / instruction)
__device__ __forceinline__ u64 ffma2(u64 a, u64 b, u64 c) {
    u64 d; asm("fma.rn.f32x2 %0, %1, %2, %3;" : "=l"(d) : "l"(a), "l"(b), "l"(c)); return d;
}

// Stage weights into shared, pair-packed over outputs with quarter-padded rows.
__device__ __forceinline__ void stage(u64* dst, const float* __restrict__ W,
                                      int NIN, int NOUT, int pairQ, int QS, int tid) {
    int total = NIN * 4 * pairQ;
    for (int idx = tid; idx < total; idx += 256) {
        int i = idx / (4 * pairQ);
        int r = idx % (4 * pairQ);
        int q = r / pairQ, p = r % pairQ;
        int j0 = 2 * (q * pairQ + p);
        float a = (j0     < NOUT) ? W[j0 * NIN + i]       : 0.0f;
        float b = (j0 + 1 < NOUT) ? W[(j0 + 1) * NIN + i] : 0.0f;
        dst[(i * 4 + q) * QS + p] = pack2(a, b);
    }
}

// Dot: h = duplicated spike pairs (s_i, s_i) in shared; ascending-i accumulation
// per output (bit-exact vs reference). PAIRQ even (>=2).
template<int NIN, int PAIRQ, int QS>
__device__ __forceinline__ void dot(const u64* __restrict__ h, const u64* __restrict__ wq, u64* acc) {
#pragma unroll
    for (int p = 0; p < PAIRQ; ++p) acc[p] = 0ull;
#pragma unroll
    for (int i = 0; i < NIN; i += 2) {
        ulonglong2 h2 = *(const ulonglong2*)(h + i);           // (s_i,s_i),(s_{i+1},s_{i+1})
#pragma unroll
        for (int p = 0; p < PAIRQ; p += 2) {
            ulonglong2 wa = *(const ulonglong2*)(wq + (i * 4) * QS + p);
            ulonglong2 wb = *(const ulonglong2*)(wq + ((i + 1) * 4) * QS + p);
            acc[p]     = ffma2(h2.x, wa.x, acc[p]);
            acc[p + 1] = ffma2(h2.x, wa.y, acc[p + 1]);
            acc[p]     = ffma2(h2.y, wb.x, acc[p]);
            acc[p + 1] = ffma2(h2.y, wb.y, acc[p + 1]);
        }
    }
}

// LIF update + store duplicated spike pairs. reset_t == spike_{t-1} (cached float s).
template<int PAIRQ>
__device__ __forceinline__ void lif_store(const u64* acc, float* m, float* s, u64* dst) {
#pragma unroll
    for (int p = 0; p < PAIRQ; ++p) {
        float a0, a1; unpack2(acc[p], a0, a1);
        float mm0 = fmaf(BETAF, m[2 * p],     a0 - s[2 * p]);
        float mm1 = fmaf(BETAF, m[2 * p + 1], a1 - s[2 * p + 1]);
        m[2 * p] = mm0; m[2 * p + 1] = mm1;
        float ns0 = mm0 > THRESHF ? 1.0f : 0.0f;
        float ns1 = mm1 > THRESHF ? 1.0f : 0.0f;
        s[2 * p] = ns0; s[2 * p + 1] = ns1;
        ulonglong2 v; v.x = pack2(ns0, ns0); v.y = pack2(ns1, ns1);
        *(ulonglong2*)(dst + 2 * p) = v;                        // STS.128
    }
}

extern __shared__ u64 smem[];

__global__ __launch_bounds__(256, 2) void lif_kernel(
    const float* __restrict__ x,
    const float* __restrict__ W1, const float* __restrict__ W2,
    const float* __restrict__ W3, const float* __restrict__ W4,
    const float* __restrict__ W5, float* __restrict__ out)
{
    int tid = threadIdx.x;
    stage(smem + W1_OFF, W1, 10, 64, 8, QS1, tid);
    stage(smem + W2_OFF, W2, 64, 32, 4, QS2, tid);
    stage(smem + W3_OFF, W3, 32, 32, 4, QS3, tid);
    stage(smem + W4_OFF, W4, 32, 16, 2, QS4, tid);
    stage(smem + W5_OFF, W5, 16,  6, 1, QS5, tid);
    __syncthreads();

    int eloc = tid >> 2;          // element within block (64 per block)
    int q    = tid & 3;           // quarter of each layer's outputs
    size_t e = (size_t)blockIdx.x * 64 + eloc;

    u64* spk = smem + SPK_OFF + eloc * ESTRIDE;
    const u64* w1q = smem + W1_OFF + q * QS1;
    const u64* w2q = smem + W2_OFF + q * QS2;
    const u64* w3q = smem + W3_OFF + q * QS3;
    const u64* w4q = smem + W4_OFF + q * QS4;
    const u64* w5q = smem + W5_OFF + q * QS5;

    // per-thread state: quarter of each layer
    float m1[16], s1[16], m2[8], s2[8], m3[8], s3[8], m4[4], s4[4], m5[2], s5[2];
#pragma unroll
    for (int k = 0; k < 16; ++k) { m1[k] = 0.f; s1[k] = 0.f; }
#pragma unroll
    for (int k = 0; k < 8; ++k)  { m2[k] = 0.f; s2[k] = 0.f; m3[k] = 0.f; s3[k] = 0.f; }
#pragma unroll
    for (int k = 0; k < 4; ++k)  { m4[k] = 0.f; s4[k] = 0.f; }
#pragma unroll
    for (int k = 0; k < 2; ++k)  { m5[k] = 0.f; s5[k] = 0.f; }

    for (int t = 0; t < T_STEPS; ++t) {
        // ---- Layer 1: x(10) -> 64, this thread computes 16 outputs (8 pairs) ----
        const float2* xp = (const float2*)(x + ((size_t)t * BATCH + e) * 10);
        float xv[10];
#pragma unroll
        for (int i = 0; i < 5; ++i) { float2 v = xp[i]; xv[2 * i] = v.x; xv[2 * i + 1] = v.y; }

        u64 acc1[8];
#pragma unroll
        for (int p = 0; p < 8; ++p) acc1[p] = 0ull;
#pragma unroll
        for (int i = 0; i < 10; ++i) {
            u64 h2 = pack2(xv[i], xv[i]);
#pragma unroll
            for (int p = 0; p < 8; p += 2) {
                ulonglong2 w = *(const ulonglong2*)(w1q + (i * 4) * QS1 + p);
                acc1[p]     = ffma2(h2, w.x, acc1[p]);
                acc1[p + 1] = ffma2(h2, w.y, acc1[p + 1]);
            }
        }
        lif_store<8>(acc1, m1, s1, spk + 0 + q * 16);
        __syncwarp();

        // ---- Layer 2: 64 -> 32 (8 outputs / thread) ----
        u64 acc2[4];
        dot<64, 4, QS2>(spk + 0, w2q, acc2);
        lif_store<4>(acc2, m2, s2, spk + 64 + q * 8);
        __syncwarp();

        // ---- Layer 3: 32 -> 32 ----
        u64 acc3[4];
        dot<32, 4, QS3>(spk + 64, w3q, acc3);
        lif_store<4>(acc3, m3, s3, spk + 96 + q * 8);
        __syncwarp();

        // ---- Layer 4: 32 -> 16 (4 outputs / thread) ----
        u64 acc4[2];
        dot<32, 2, QS4>(spk + 96, w4q, acc4);
        lif_store<2>(acc4, m4, s4, spk + 128 + q * 4);
        __syncwarp();

        // ---- Layer 5: 16 -> 6 (padded to 8; outputs {2q, 2q+1}) ----
        u64 acc5 = 0ull;
#pragma unroll
        for (int i = 0; i < 16; i += 2) {
            ulonglong2 h2 = *(const ulonglong2*)(spk + 128 + i);
            acc5 = ffma2(h2.x, w5q[(i * 4) * QS5], acc5);
            acc5 = ffma2(h2.y, w5q[((i + 1) * 4) * QS5], acc5);
        }
        {
            float a0, a1; unpack2(acc5, a0, a1);
            float mm0 = fmaf(BETAF, m5[0], a0 - s5[0]);
            float mm1 = fmaf(BETAF, m5[1], a1 - s5[1]);
            m5[0] = mm0; m5[1] = mm1;
            float ns0 = mm0 > THRESHF ? 1.0f : 0.0f;
            float ns1 = mm1 > THRESHF ? 1.0f : 0.0f;
            s5[0] = ns0; s5[1] = ns1;
            if (q < 3) {
                float2 o; o.x = ns0; o.y = ns1;
                *(float2*)(out + ((size_t)t * BATCH + e) * 6 + q * 2) = o;
            }
        }
        // next t's L1 overwrite is fenced by the syncwarp after L1's STS
    }
}

extern "C" void kernel_launch(void* const* d_in, const int* in_sizes, int n_in,
                              void* d_out, int out_size) {
    const float *x = nullptr, *W1 = nullptr, *W2 = nullptr, *W3 = nullptr,
                *W4 = nullptr, *W5 = nullptr;
    for (int i = 0; i < n_in; ++i) {
        const float* p = (const float*)d_in[i];
        switch (in_sizes[i]) {
            case 52428800: x  = p; break;  // (20, 262144, 10)
            case 640:      W1 = p; break;  // (64, 10)
            case 2048:     W2 = p; break;  // (32, 64)
            case 1024:     W3 = p; break;  // (32, 32)
            case 512:      W4 = p; break;  // (16, 32)
            case 96:       W5 = p; break;  // (6, 16)
            default: break;
        }
    }
    float* out = (float*)d_out;

    static int smem_set = 0;
    (void)smem_set; // deterministic: set attribute every call (host-side, not a stream op)
    cudaFuncSetAttribute(lif_kernel, cudaFuncAttributeMaxDynamicSharedMemorySize,
                         SMEM_U64 * (int)sizeof(u64));

    // 4 threads per element, 64 elements per 256-thread block
    lif_kernel<<<BATCH / 64, 256, SMEM_U64 * sizeof(u64)>>>(x, W1, W2, W3, W4, W5, out);
}

// round 3
// speedup vs baseline: 1.9108x; 1.9108x over previous
#include <cuda_runtime.h>

#define BATCH   262144
#define T_STEPS 20
#define BETAF   0.9f
#define THRESHF 1.0f

using u32 = unsigned int;
using u64 = unsigned long long;

__device__ __forceinline__ u64 pack2(float lo, float hi) {
    u64 r; asm("mov.b64 %0, {%1, %2};" : "=l"(r) : "f"(lo), "f"(hi)); return r;
}
__device__ __forceinline__ void unpack2(u64 v, float &lo, float &hi) {
    asm("mov.b64 {%0, %1}, %2;" : "=f"(lo), "=f"(hi) : "l"(v));
}
// Packed dual fp32 FMA (2 MACs / instruction on the fma pipe)
__device__ __forceinline__ u64 ffma2(u64 a, u64 b, u64 c) {
    u64 d; asm("fma.rn.f32x2 %0, %1, %2, %3;" : "=l"(d) : "l"(a), "l"(b), "l"(c)); return d;
}

// ---- static smem weight store, pair-packed, half-major ----
// layer row (i, half) holds P2 pairs contiguously: w[(i*2+half)*P2 + p] =
// (W[2*(half*P2+p)][i], W[2*(half*P2+p)+1][i])
__shared__ u64 sW1[10 * 2 * 16];  // 10 -> 64
__shared__ u64 sW2[64 * 2 * 8];   // 64 -> 32
__shared__ u64 sW3[32 * 2 * 8];   // 32 -> 32
__shared__ u64 sW4[32 * 2 * 4];   // 32 -> 16
__shared__ u64 sW5[16 * 2 * 2];   // 16 -> 6 (padded to 8 outs)

__device__ __forceinline__ void stage(u64* dst, const float* __restrict__ W,
                                      int NIN, int NOUT, int P2, int tid, int nthr) {
    int total = NIN * 2 * P2;
    for (int idx = tid; idx < total; idx += nthr) {
        int i = idx / (2 * P2);
        int r = idx % (2 * P2);
        int h = r / P2, p = r % P2;
        int j0 = 2 * (h * P2 + p);
        float a = (j0     < NOUT) ? W[j0 * NIN + i]       : 0.0f;
        float b = (j0 + 1 < NOUT) ? W[(j0 + 1) * NIN + i] : 0.0f;
        dst[(i * 2 + h) * P2 + p] = pack2(a, b);
    }
}

// LIF over PAIRS output pairs: subtract-reset from OLD mem, update mem,
// return spike bitmask (bit n = neuron 2p+comp). Same formula/order as prior rounds.
template<int PAIRS>
__device__ __forceinline__ u32 lif_mask(const u64* acc, float* m) {
    u32 msk = 0;
#pragma unroll
    for (int p = 0; p < PAIRS; ++p) {
        float a0, a1; unpack2(acc[p], a0, a1);
        float r0 = m[2 * p]     > THRESHF ? THRESHF : 0.0f;
        float r1 = m[2 * p + 1] > THRESHF ? THRESHF : 0.0f;
        float mm0 = fmaf(BETAF, m[2 * p],     a0 - r0);
        float mm1 = fmaf(BETAF, m[2 * p + 1], a1 - r1);
        m[2 * p] = mm0; m[2 * p + 1] = mm1;
        if (mm0 > THRESHF) msk |= 1u << (2 * p);
        if (mm1 > THRESHF) msk |= 1u << (2 * p + 1);
    }
    return msk;
}

// dup-pair (h, h) from mask bit i (literal i via unrolled caller)
__device__ __forceinline__ u64 hdup(u32 mask, int i) {
    float h = (mask & (1u << i)) ? 1.0f : 0.0f;
    return pack2(h, h);
}

// 32-input block: mask bits 0..31 ascending, P2 pairs per half (even), 2 distinct
// warp addresses (half) -> broadcast-cheap LDS.128.
template<int P2>
__device__ __forceinline__ void dot32(u32 mask, const u64* __restrict__ wbase,
                                      int half, u64* acc) {
#pragma unroll
    for (int i = 0; i < 32; ++i) {
        u64 h2 = hdup(mask, i);
        const ulonglong2* wp = (const ulonglong2*)(wbase + (i * 2 + half) * P2);
#pragma unroll
        for (int p2 = 0; p2 < P2 / 2; ++p2) {
            ulonglong2 w = wp[p2];
            acc[2 * p2]     = ffma2(h2, w.x, acc[2 * p2]);
            acc[2 * p2 + 1] = ffma2(h2, w.y, acc[2 * p2 + 1]);
        }
    }
}
template<int P2>
__device__ __forceinline__ void dot16(u32 mask, const u64* __restrict__ wbase,
                                      int half, u64* acc) {
#pragma unroll
    for (int i = 0; i < 16; ++i) {
        u64 h2 = hdup(mask, i);
        const ulonglong2* wp = (const ulonglong2*)(wbase + (i * 2 + half) * P2);
#pragma unroll
        for (int p2 = 0; p2 < P2 / 2; ++p2) {
            ulonglong2 w = wp[p2];
            acc[2 * p2]     = ffma2(h2, w.x, acc[2 * p2]);
            acc[2 * p2 + 1] = ffma2(h2, w.y, acc[2 * p2 + 1]);
        }
    }
}

__global__ __launch_bounds__(128, 3) void lif_kernel(
    const float* __restrict__ x,
    const float* __restrict__ W1, const float* __restrict__ W2,
    const float* __restrict__ W3, const float* __restrict__ W4,
    const float* __restrict__ W5, float* __restrict__ out)
{
    int tid = threadIdx.x;
    stage(sW1, W1, 10, 64, 16, tid, 128);
    stage(sW2, W2, 64, 32,  8, tid, 128);
    stage(sW3, W3, 32, 32,  8, tid, 128);
    stage(sW4, W4, 32, 16,  4, tid, 128);
    stage(sW5, W5, 16,  6,  2, tid, 128);
    __syncthreads();

    int half = tid & 1;                         // adjacent lanes = two halves of one element
    size_t e = (size_t)blockIdx.x * 64 + (tid >> 1);

    // per-thread membrane state: half of each layer
    float m1[32], m2[16], m3[16], m4[8], m5[4];
#pragma unroll
    for (int k = 0; k < 32; ++k) m1[k] = 0.f;
#pragma unroll
    for (int k = 0; k < 16; ++k) { m2[k] = 0.f; m3[k] = 0.f; }
#pragma unroll
    for (int k = 0; k < 8; ++k)  m4[k] = 0.f;
#pragma unroll
    for (int k = 0; k < 4; ++k)  m5[k] = 0.f;

#pragma unroll 1
    for (int t = 0; t < T_STEPS; ++t) {
        // ---- x[t, e, 0:10] as dup-pairs ----
        const float2* xp = (const float2*)(x + ((size_t)t * BATCH + e) * 10);
        u64 xd[10];
#pragma unroll
        for (int i = 0; i < 5; ++i) {
            float2 v = xp[i];
            xd[2 * i]     = pack2(v.x, v.x);
            xd[2 * i + 1] = pack2(v.y, v.y);
        }

        // ---- Layer 1: 10 -> 64 (16 pairs per half) ----
        u64 acc1[16];
#pragma unroll
        for (int p = 0; p < 16; ++p) acc1[p] = 0ull;
#pragma unroll
        for (int i = 0; i < 10; ++i) {
            const ulonglong2* wp = (const ulonglong2*)(sW1 + (i * 2 + half) * 16);
#pragma unroll
            for (int p2 = 0; p2 < 8; ++p2) {
                ulonglong2 w = wp[p2];
                acc1[2 * p2]     = ffma2(xd[i], w.x, acc1[2 * p2]);
                acc1[2 * p2 + 1] = ffma2(xd[i], w.y, acc1[2 * p2 + 1]);
            }
        }
        u32 msk1 = lif_mask<16>(acc1, m1);              // 32 bits (this half)
        u32 oth1 = __shfl_xor_sync(0xffffffffu, msk1, 1);
        u32 lo1 = half ? oth1 : msk1;                   // L1 outputs 0..31
        u32 hi1 = half ? msk1 : oth1;                   // L1 outputs 32..63

        // ---- Layer 2: 64 -> 32 (8 pairs per half) ----
        u64 acc2[8];
#pragma unroll
        for (int p = 0; p < 8; ++p) acc2[p] = 0ull;
        dot32<8>(lo1, sW2, half, acc2);
        dot32<8>(hi1, sW2 + 32 * 2 * 8, half, acc2);
        u32 msk2 = lif_mask<8>(acc2, m2);               // 16 bits
        u32 oth2 = __shfl_xor_sync(0xffffffffu, msk2, 1);
        u32 full2 = half ? (oth2 | (msk2 << 16)) : (msk2 | (oth2 << 16));

        // ---- Layer 3: 32 -> 32 ----
        u64 acc3[8];
#pragma unroll
        for (int p = 0; p < 8; ++p) acc3[p] = 0ull;
        dot32<8>(full2, sW3, half, acc3);
        u32 msk3 = lif_mask<8>(acc3, m3);
        u32 oth3 = __shfl_xor_sync(0xffffffffu, msk3, 1);
        u32 full3 = half ? (oth3 | (msk3 << 16)) : (msk3 | (oth3 << 16));

        // ---- Layer 4: 32 -> 16 (4 pairs per half) ----
        u64 acc4[4];
#pragma unroll
        for (int p = 0; p < 4; ++p) acc4[p] = 0ull;
        dot32<4>(full3, sW4, half, acc4);
        u32 msk4 = lif_mask<4>(acc4, m4);               // 8 bits
        u32 oth4 = __shfl_xor_sync(0xffffffffu, msk4, 1);
        u32 full4 = half ? (oth4 | (msk4 << 8)) : (msk4 | (oth4 << 8));

        // ---- Layer 5: 16 -> 6 (padded to 8; 2 pairs per half) ----
        u64 acc5[2];
        acc5[0] = 0ull; acc5[1] = 0ull;
        dot16<2>(full4, sW5, half, acc5);
        float s[4];
#pragma unroll
        for (int p = 0; p < 2; ++p) {
            float a0, a1; unpack2(acc5[p], a0, a1);
            float r0 = m5[2 * p]     > THRESHF ? THRESHF : 0.0f;
            float r1 = m5[2 * p + 1] > THRESHF ? THRESHF : 0.0f;
            float mm0 = fmaf(BETAF, m5[2 * p],     a0 - r0);
            float mm1 = fmaf(BETAF, m5[2 * p + 1], a1 - r1);
            m5[2 * p] = mm0; m5[2 * p + 1] = mm1;
            s[2 * p]     = mm0 > THRESHF ? 1.0f : 0.0f;
            s[2 * p + 1] = mm1 > THRESHF ? 1.0f : 0.0f;
        }

        // ---- out[t, e, 0:6]: half0 -> 0..3, half1 -> 4..5 ----
        float* op = out + ((size_t)t * BATCH + e) * 6;
        if (!half) {
            *(float2*)(op)     = make_float2(s[0], s[1]);
            *(float2*)(op + 2) = make_float2(s[2], s[3]);
        } else {
            *(float2*)(op + 4) = make_float2(s[0], s[1]);
        }
    }
}

extern "C" void kernel_launch(void* const* d_in, const int* in_sizes, int n_in,
                              void* d_out, int out_size) {
    const float *x = nullptr, *W1 = nullptr, *W2 = nullptr, *W3 = nullptr,
                *W4 = nullptr, *W5 = nullptr;
    for (int i = 0; i < n_in; ++i) {
        const float* p = (const float*)d_in[i];
        switch (in_sizes[i]) {
            case 52428800: x  = p; break;  // (20, 262144, 10)
            case 640:      W1 = p; break;  // (64, 10)
            case 2048:     W2 = p; break;  // (32, 64)
            case 1024:     W3 = p; break;  // (32, 32)
            case 512:      W4 = p; break;  // (16, 32)
            case 96:       W5 = p; break;  // (6, 16)
            default: break;
        }
    }
    float* out = (float*)d_out;
    // 2 threads per element, 64 elements per 128-thread block
    lif_kernel<<<BATCH / 64, 128>>>(x, W1, W2, W3, W4, W5, out);
}